// round 2
// baseline (speedup 1.0000x reference)
#include <cuda_runtime.h>

#define T_STEPS 100
#define BATCH   32
#define N_IN    1024
#define N_OUT   512
#define KDIM    (T_STEPS * BATCH)   // 3200
#define SK      8                   // split-K factor
#define KSPLIT  (KDIM / SK)         // 400

// Scratch (device globals — no allocation allowed in kernel_launch)
__device__ float g_preTr[KDIM * N_IN];            // [K, 1024]
__device__ float g_postTr[KDIM * N_OUT];          // [K, 512]
__device__ float g_part1[SK][N_OUT * N_IN];       // LTP partials per split
__device__ float g_part2[SK][N_OUT * N_IN];       // LTD partials per split

// ---------------- packed f32x2 helpers ----------------
__device__ __forceinline__ void unpack2(unsigned long long v, float& lo, float& hi) {
    asm("mov.b64 {%0, %1}, %2;" : "=f"(lo), "=f"(hi) : "l"(v));
}
__device__ __forceinline__ unsigned long long ffma2(unsigned long long a,
                                                    unsigned long long b,
                                                    unsigned long long c) {
    unsigned long long d;
    asm("fma.rn.f32x2 %0, %1, %2, %3;" : "=l"(d) : "l"(a), "l"(b), "l"(c));
    return d;
}

// ---------------- Kernel 1: trace recurrences ----------------
__global__ void stdp_trace_kernel(const float* __restrict__ preS,
                                  const float* __restrict__ postS,
                                  const float* __restrict__ preTr0,
                                  const float* __restrict__ postTr0,
                                  float* __restrict__ out) {
    const float DECAY = 0.95122942450071400910f;  // exp(-1/20)
    const int NPRE  = BATCH * N_IN;    // 32768
    const int NPOST = BATCH * N_OUT;   // 16384
    int idx = blockIdx.x * blockDim.x + threadIdx.x;
    if (idx < NPRE) {
        float tr = preTr0[idx];
        #pragma unroll 5
        for (int t = 0; t < T_STEPS; t++) {
            tr = fmaf(tr, DECAY, preS[t * NPRE + idx]);
            g_preTr[t * NPRE + idx] = tr;
        }
        out[N_OUT * N_IN + idx] = tr;                 // final pre_trace
    } else if (idx < NPRE + NPOST) {
        int j = idx - NPRE;
        float tr = postTr0[j];
        #pragma unroll 5
        for (int t = 0; t < T_STEPS; t++) {
            tr = fmaf(tr, DECAY, postS[t * NPOST + j]);
            g_postTr[t * NPOST + j] = tr;
        }
        out[N_OUT * N_IN + NPRE + j] = tr;            // final post_trace
    }
}

// ---------------- Kernel 2: split-K fused dual GEMM ----------------
// C1[o,i] += sum_{k in split} postS[k,o]*preTr[k,i]   (LTP)
// C2[o,i] += sum_{k in split} postTr[k,o]*preS[k,i]   (LTD)
#define BM 64
#define BN 64
#define BK 16

__global__ __launch_bounds__(128, 3)
void stdp_gemm_kernel(const float* __restrict__ postS,   // [K, 512]
                      const float* __restrict__ preS) {  // [K, 1024]
    // A tiles stored DUPLICATED: sA[k][2*m] == sA[k][2*m+1] == A[k][m]
    __shared__ __align__(16) float sA1[BK][BM * 2];  // postS  (12 KB total A)
    __shared__ __align__(16) float sA2[BK][BM * 2];  // postTr
    __shared__ __align__(16) float sB1[BK][BN];      // preTr
    __shared__ __align__(16) float sB2[BK][BN];      // preS

    const float* preTr  = g_preTr;
    const float* postTr = g_postTr;

    const int tid = threadIdx.x;
    const int tx  = tid & 7;    // n-group
    const int ty  = tid >> 3;   // m-group
    const int m0  = ty * 4;
    const int n0  = tx * 8;
    const int bM  = blockIdx.y * BM;
    const int bN  = blockIdx.x * BN;
    const int s   = blockIdx.z;           // split index
    const int k0  = s * KSPLIT;

    const int lrow = tid >> 4;  // 0..7
    const int lcol = tid & 15;  // float4 index within 64-float row

    unsigned long long acc1[4][4], acc2[4][4];
    #pragma unroll
    for (int m = 0; m < 4; m++)
        #pragma unroll
        for (int p = 0; p < 4; p++) { acc1[m][p] = 0ull; acc2[m][p] = 0ull; }

    for (int kt = k0; kt < k0 + KSPLIT; kt += BK) {
        #pragma unroll
        for (int pss = 0; pss < 2; pss++) {
            int r = lrow + pss * 8;
            int k = kt + r;
            float4 a1 = ((const float4*)(postS  + (size_t)k * N_OUT + bM))[lcol];
            float4 a2 = ((const float4*)(postTr + (size_t)k * N_OUT + bM))[lcol];
            // store duplicated pairs: (x,x,y,y) and (z,z,w,w)
            ((float4*)&sA1[r][0])[lcol * 2]     = make_float4(a1.x, a1.x, a1.y, a1.y);
            ((float4*)&sA1[r][0])[lcol * 2 + 1] = make_float4(a1.z, a1.z, a1.w, a1.w);
            ((float4*)&sA2[r][0])[lcol * 2]     = make_float4(a2.x, a2.x, a2.y, a2.y);
            ((float4*)&sA2[r][0])[lcol * 2 + 1] = make_float4(a2.z, a2.z, a2.w, a2.w);
            ((float4*)&sB1[r][0])[lcol] =
                ((const float4*)(preTr  + (size_t)k * N_IN  + bN))[lcol];
            ((float4*)&sB2[r][0])[lcol] =
                ((const float4*)(preS   + (size_t)k * N_IN  + bN))[lcol];
        }
        __syncthreads();

        #pragma unroll
        for (int kk = 0; kk < BK; kk++) {
            ulonglong2 a1p0 = *(const ulonglong2*)&sA1[kk][m0 * 2];
            ulonglong2 a1p1 = *(const ulonglong2*)&sA1[kk][m0 * 2 + 4];
            ulonglong2 a2p0 = *(const ulonglong2*)&sA2[kk][m0 * 2];
            ulonglong2 a2p1 = *(const ulonglong2*)&sA2[kk][m0 * 2 + 4];
            ulonglong2 t0 = *(const ulonglong2*)&sB1[kk][n0];
            ulonglong2 t1 = *(const ulonglong2*)&sB1[kk][n0 + 4];
            ulonglong2 u0 = *(const ulonglong2*)&sB2[kk][n0];
            ulonglong2 u1 = *(const ulonglong2*)&sB2[kk][n0 + 4];
            unsigned long long a1d[4] = {a1p0.x, a1p0.y, a1p1.x, a1p1.y};
            unsigned long long a2d[4] = {a2p0.x, a2p0.y, a2p1.x, a2p1.y};
            unsigned long long b1v[4] = {t0.x, t0.y, t1.x, t1.y};
            unsigned long long b2v[4] = {u0.x, u0.y, u1.x, u1.y};
            #pragma unroll
            for (int m = 0; m < 4; m++)
                #pragma unroll
                for (int p = 0; p < 4; p++) {
                    acc1[m][p] = ffma2(a1d[m], b1v[p], acc1[m][p]);
                    acc2[m][p] = ffma2(a2d[m], b2v[p], acc2[m][p]);
                }
        }
        __syncthreads();
    }

    // write split partials
    #pragma unroll
    for (int m = 0; m < 4; m++) {
        size_t off = (size_t)(bM + m0 + m) * N_IN + bN + n0;
        float r1[8], r2[8];
        #pragma unroll
        for (int p = 0; p < 4; p++) {
            unpack2(acc1[m][p], r1[2 * p], r1[2 * p + 1]);
            unpack2(acc2[m][p], r2[2 * p], r2[2 * p + 1]);
        }
        *(float4*)&g_part1[s][off]     = make_float4(r1[0], r1[1], r1[2], r1[3]);
        *(float4*)&g_part1[s][off + 4] = make_float4(r1[4], r1[5], r1[6], r1[7]);
        *(float4*)&g_part2[s][off]     = make_float4(r2[0], r2[1], r2[2], r2[3]);
        *(float4*)&g_part2[s][off + 4] = make_float4(r2[4], r2[5], r2[6], r2[7]);
    }
}

// ---------------- Kernel 3: split reduction + STDP epilogue ----------------
__global__ void stdp_reduce_kernel(const float* __restrict__ weight,
                                   float* __restrict__ out) {
    const float LRP = 1e-4f, LRD = -1e-4f, invB = 1.0f / 32.0f;
    int i = blockIdx.x * blockDim.x + threadIdx.x;   // float4 index
    size_t off = (size_t)i * 4;
    float4 c1 = make_float4(0.f, 0.f, 0.f, 0.f);
    float4 c2 = make_float4(0.f, 0.f, 0.f, 0.f);
    #pragma unroll
    for (int s = 0; s < SK; s++) {
        float4 p1 = *(const float4*)&g_part1[s][off];
        float4 p2 = *(const float4*)&g_part2[s][off];
        c1.x += p1.x; c1.y += p1.y; c1.z += p1.z; c1.w += p1.w;
        c2.x += p2.x; c2.y += p2.y; c2.z += p2.z; c2.w += p2.w;
    }
    float4 w = *(const float4*)(weight + off);
    float4 r;
    r.x = (LRP * (1.0f - w.x) * c1.x + LRD * w.x * c2.x) * invB;
    r.y = (LRP * (1.0f - w.y) * c1.y + LRD * w.y * c2.y) * invB;
    r.z = (LRP * (1.0f - w.z) * c1.z + LRD * w.z * c2.z) * invB;
    r.w = (LRP * (1.0f - w.w) * c1.w + LRD * w.w * c2.w) * invB;
    *(float4*)(out + off) = r;
}

// ---------------- launch ----------------
extern "C" void kernel_launch(void* const* d_in, const int* in_sizes, int n_in,
                              void* d_out, int out_size) {
    const float *weight = nullptr, *preS = nullptr, *postS = nullptr;
    const float *preTr0 = nullptr, *postTr0 = nullptr;
    for (int j = 0; j < n_in; j++) {
        switch (in_sizes[j]) {
            case N_OUT * N_IN:              weight  = (const float*)d_in[j]; break;
            case T_STEPS * BATCH * N_IN:    preS    = (const float*)d_in[j]; break;
            case T_STEPS * BATCH * N_OUT:   postS   = (const float*)d_in[j]; break;
            case BATCH * N_IN:              preTr0  = (const float*)d_in[j]; break;
            case BATCH * N_OUT:             postTr0 = (const float*)d_in[j]; break;
            default: break;
        }
    }
    float* out = (float*)d_out;

    // 1) traces (also writes final pre/post traces into d_out tail)
    stdp_trace_kernel<<<192, 256>>>(preS, postS, preTr0, postTr0, out);

    // 2) split-K fused dual GEMM -> partials
    dim3 grid(N_IN / BN, N_OUT / BM, SK);   // (16, 8, 8) = 1024 blocks
    stdp_gemm_kernel<<<grid, 128>>>(postS, preS);

    // 3) reduce partials + STDP epilogue -> dw
    stdp_reduce_kernel<<<(N_OUT * N_IN / 4) / 256, 256>>>(weight, out);
}

// round 3
// speedup vs baseline: 2.8894x; 2.8894x over previous
#include <cuda_runtime.h>

#define T_STEPS 100
#define BATCH   32
#define N_IN    1024
#define N_OUT   512
#define KDIM    (T_STEPS * BATCH)   // 3200
#define NPRE    (BATCH * N_IN)      // 32768
#define NPOST   (BATCH * N_OUT)    // 16384
#define CAP     1024                // max spikes per row/col list (mean ~160)

// Scratch (device globals — no allocation allowed)
__device__ float g_preTr[KDIM * N_IN];     // [k][i]
__device__ float g_postTr[KDIM * N_OUT];   // [k][o]
__device__ int   g_cnt1[N_OUT];            // |K_o| for postS
__device__ int   g_idx1[N_OUT][CAP];
__device__ int   g_cnt2[N_IN];             // |K_i| for preS
__device__ int   g_idx2[N_IN][CAP];
__device__ float g_c1[N_OUT * N_IN];       // LTP sums [o][i]
__device__ float g_c2T[N_IN * N_OUT];      // LTD sums transposed [i][o]

// ---------------- Kernel 1: trace recurrences ----------------
__global__ void stdp_trace_kernel(const float* __restrict__ preS,
                                  const float* __restrict__ postS,
                                  const float* __restrict__ preTr0,
                                  const float* __restrict__ postTr0,
                                  float* __restrict__ out) {
    const float DECAY = 0.95122942450071400910f;  // exp(-1/20)
    int idx = blockIdx.x * blockDim.x + threadIdx.x;
    if (idx < NPRE) {
        float tr = preTr0[idx];
        #pragma unroll 5
        for (int t = 0; t < T_STEPS; t++) {
            tr = fmaf(tr, DECAY, preS[t * NPRE + idx]);
            g_preTr[t * NPRE + idx] = tr;
        }
        out[N_OUT * N_IN + idx] = tr;                 // final pre_trace
    } else if (idx < NPRE + NPOST) {
        int j = idx - NPRE;
        float tr = postTr0[j];
        #pragma unroll 5
        for (int t = 0; t < T_STEPS; t++) {
            tr = fmaf(tr, DECAY, postS[t * NPOST + j]);
            g_postTr[t * NPOST + j] = tr;
        }
        out[N_OUT * N_IN + NPRE + j] = tr;            // final post_trace
    }
}

// ---------------- Kernel 2: spike index compaction (deterministic) ---------
// Warp w < 16 handles o-columns [w*32, w*32+32) of postS  -> g_idx1/g_cnt1
// Warp w >= 16 handles i-columns of preS                  -> g_idx2/g_cnt2
// Per 32x32 tile: 32 coalesced row loads + ballots; lane ends with a 32-bit
// k-occupancy mask for its column; appends set bits in k order.
__global__ void stdp_scan_kernel(const float* __restrict__ postS,
                                 const float* __restrict__ preS) {
    int w    = blockIdx.x * (blockDim.x >> 5) + (threadIdx.x >> 5);
    int lane = threadIdx.x & 31;
    const float* src;
    int stride, col0;
    int* cnt; int (*idx)[CAP];
    if (w < N_OUT / 32) {
        src = postS; stride = N_OUT; col0 = w * 32;
        cnt = g_cnt1; idx = g_idx1;
    } else {
        int wi = w - N_OUT / 32;
        src = preS; stride = N_IN; col0 = wi * 32;
        cnt = g_cnt2; idx = g_idx2;
    }
    int col = col0 + lane;
    int c = 0;
    for (int tile = 0; tile < KDIM / 32; tile++) {
        int k0 = tile * 32;
        unsigned mask = 0u;
        #pragma unroll
        for (int j = 0; j < 32; j++) {
            float v = src[(size_t)(k0 + j) * stride + col];
            unsigned m = __ballot_sync(0xFFFFFFFFu, v != 0.0f);
            mask |= ((m >> lane) & 1u) << j;
        }
        while (mask) {
            int j = __ffs(mask) - 1;
            mask &= mask - 1u;
            if (c < CAP) idx[col][c] = k0 + j;
            c++;
        }
    }
    cnt[col] = (c < CAP) ? c : CAP;
}

// ---------------- Kernel 3: sparse gather-sums ----------------
// blocks [0, 512):    C1[o][:]  = sum over K_o of preTr rows   (256 thr, float4)
// blocks [512, 1536): C2T[i][:] = sum over K_i of postTr rows  (256 thr, float2)
__global__ __launch_bounds__(256)
void stdp_gather_kernel() {
    __shared__ int sidx[CAP];
    int b   = blockIdx.x;
    int tid = threadIdx.x;

    if (b < N_OUT) {
        int o = b;
        int cnt = g_cnt1[o];
        for (int j = tid; j < cnt; j += 256) sidx[j] = g_idx1[o][j];
        __syncthreads();
        float4 acc = make_float4(0.f, 0.f, 0.f, 0.f);
        int i4 = tid * 4;
        int j = 0;
        for (; j + 4 <= cnt; j += 4) {
            float4 a = *(const float4*)&g_preTr[(size_t)sidx[j]     * N_IN + i4];
            float4 c = *(const float4*)&g_preTr[(size_t)sidx[j + 1] * N_IN + i4];
            float4 d = *(const float4*)&g_preTr[(size_t)sidx[j + 2] * N_IN + i4];
            float4 e = *(const float4*)&g_preTr[(size_t)sidx[j + 3] * N_IN + i4];
            acc.x += a.x + c.x; acc.y += a.y + c.y;
            acc.z += a.z + c.z; acc.w += a.w + c.w;
            acc.x += d.x + e.x; acc.y += d.y + e.y;
            acc.z += d.z + e.z; acc.w += d.w + e.w;
        }
        for (; j < cnt; j++) {
            float4 a = *(const float4*)&g_preTr[(size_t)sidx[j] * N_IN + i4];
            acc.x += a.x; acc.y += a.y; acc.z += a.z; acc.w += a.w;
        }
        *(float4*)&g_c1[(size_t)o * N_IN + i4] = acc;
    } else {
        int i = b - N_OUT;
        int cnt = g_cnt2[i];
        for (int j = tid; j < cnt; j += 256) sidx[j] = g_idx2[i][j];
        __syncthreads();
        float2 acc = make_float2(0.f, 0.f);
        int o2 = tid * 2;
        int j = 0;
        for (; j + 4 <= cnt; j += 4) {
            float2 a = *(const float2*)&g_postTr[(size_t)sidx[j]     * N_OUT + o2];
            float2 c = *(const float2*)&g_postTr[(size_t)sidx[j + 1] * N_OUT + o2];
            float2 d = *(const float2*)&g_postTr[(size_t)sidx[j + 2] * N_OUT + o2];
            float2 e = *(const float2*)&g_postTr[(size_t)sidx[j + 3] * N_OUT + o2];
            acc.x += a.x + c.x + d.x + e.x;
            acc.y += a.y + c.y + d.y + e.y;
        }
        for (; j < cnt; j++) {
            float2 a = *(const float2*)&g_postTr[(size_t)sidx[j] * N_OUT + o2];
            acc.x += a.x; acc.y += a.y;
        }
        *(float2*)&g_c2T[(size_t)i * N_OUT + o2] = acc;
    }
}

// ---------------- Kernel 4: transpose C2T + STDP epilogue ----------------
// dw[o][i] = (LRP*(1-w)*C1[o][i] + LRD*w*C2T[i][o]) / B
__global__ void stdp_epilogue_kernel(const float* __restrict__ weight,
                                     float* __restrict__ out) {
    __shared__ float tile[32][33];
    int bo = blockIdx.y * 32;   // o block
    int bi = blockIdx.x * 32;   // i block
    int tx = threadIdx.x;       // 0..31
    int ty = threadIdx.y;       // 0..7
    #pragma unroll
    for (int r = 0; r < 4; r++) {
        int i = bi + ty + r * 8;
        tile[ty + r * 8][tx] = g_c2T[(size_t)i * N_OUT + bo + tx];
    }
    __syncthreads();
    const float LRP = 1e-4f, LRD = -1e-4f, invB = 1.0f / 32.0f;
    #pragma unroll
    for (int r = 0; r < 4; r++) {
        int o = bo + ty + r * 8;
        size_t off = (size_t)o * N_IN + bi + tx;
        float c1 = g_c1[off];
        float c2 = tile[tx][ty + r * 8];
        float w  = weight[off];
        out[off] = (LRP * (1.0f - w) * c1 + LRD * w * c2) * invB;
    }
}

// ---------------- launch ----------------
extern "C" void kernel_launch(void* const* d_in, const int* in_sizes, int n_in,
                              void* d_out, int out_size) {
    const float *weight = nullptr, *preS = nullptr, *postS = nullptr;
    const float *preTr0 = nullptr, *postTr0 = nullptr;
    for (int j = 0; j < n_in; j++) {
        switch (in_sizes[j]) {
            case N_OUT * N_IN:              weight  = (const float*)d_in[j]; break;
            case T_STEPS * BATCH * N_IN:    preS    = (const float*)d_in[j]; break;
            case T_STEPS * BATCH * N_OUT:   postS   = (const float*)d_in[j]; break;
            case BATCH * N_IN:              preTr0  = (const float*)d_in[j]; break;
            case BATCH * N_OUT:             postTr0 = (const float*)d_in[j]; break;
            default: break;
        }
    }
    float* out = (float*)d_out;

    // 1) traces (also writes final pre/post traces into d_out tail)
    stdp_trace_kernel<<<192, 256>>>(preS, postS, preTr0, postTr0, out);

    // 2) deterministic spike-list compaction (independent of traces)
    stdp_scan_kernel<<<6, 256>>>(postS, preS);

    // 3) sparse gather-sums: C1 and C2^T
    stdp_gather_kernel<<<N_OUT + N_IN, 256>>>();

    // 4) transpose-combine epilogue -> dw
    dim3 eg(N_IN / 32, N_OUT / 32), eb(32, 8);
    stdp_epilogue_kernel<<<eg, eb>>>(weight, out);
}